// round 1
// baseline (speedup 1.0000x reference)
#include <cuda_runtime.h>
#include <math.h>

// Problem constants
#define GRID_H 13
#define GRID_W 13
#define NBOX   5
#define NCLASS 80
#define NELEM  85            // 5 + 80
#define NT     50            // true boxes per batch
#define CELLS_PER_BATCH (GRID_H * GRID_W * NBOX)   // 845
#define NBATCH 256

__constant__ float c_anchors[10] = {
    0.57273f, 0.677385f, 1.87446f, 2.06253f, 3.33843f,
    5.47434f, 7.88282f, 3.52778f, 9.77052f, 9.16828f
};

// Global accumulators: 0 nb_coord, 1 nb_conf, 2 nb_class, 3 s_xy, 4 s_wh, 5 s_conf, 6 s_class
__device__ float g_acc[7];

__global__ void zero_acc_kernel() {
    if (threadIdx.x < 7) g_acc[threadIdx.x] = 0.0f;
}

__device__ __forceinline__ float warp_max(float v) {
    #pragma unroll
    for (int o = 16; o > 0; o >>= 1) v = fmaxf(v, __shfl_xor_sync(0xFFFFFFFFu, v, o));
    return v;
}
__device__ __forceinline__ float warp_sum(float v) {
    #pragma unroll
    for (int o = 16; o > 0; o >>= 1) v += __shfl_xor_sync(0xFFFFFFFFu, v, o);
    return v;
}
__device__ __forceinline__ float sigmoidf(float x) {
    return 1.0f / (1.0f + expf(-x));
}

__global__ __launch_bounds__(1024)
void yolo_loss_kernel(const float* __restrict__ y_true,
                      const float* __restrict__ y_pred,
                      const float* __restrict__ true_boxes) {
    __shared__ float s_tb[NT * 4];   // true boxes for this batch
    __shared__ float s_acc[7];

    const int b    = blockIdx.y;
    const int warp = threadIdx.x >> 5;
    const int lane = threadIdx.x & 31;

    if (threadIdx.x < NT * 4)
        s_tb[threadIdx.x] = true_boxes[b * (NT * 4) + threadIdx.x];
    if (threadIdx.x < 7) s_acc[threadIdx.x] = 0.0f;
    __syncthreads();

    const int cell_in_b = blockIdx.x * (blockDim.x >> 5) + warp;

    if (cell_in_b < CELLS_PER_BATCH) {
        // decompose (h, w, box)
        const int box = cell_in_b % NBOX;
        const int w   = (cell_in_b / NBOX) % GRID_W;
        const int h   = cell_in_b / (NBOX * GRID_W);

        const long base = (long)(b * CELLS_PER_BATCH + cell_in_b) * NELEM;

        // lane-strided coalesced loads of the 85-vector from both tensors
        const int c0 = lane, c1 = lane + 32, c2 = lane + 64;
        const bool has2 = (c2 < NELEM);
        const float tp0 = y_pred[base + c0];
        const float tp1 = y_pred[base + c1];
        const float tp2 = has2 ? y_pred[base + c2] : 0.0f;
        const float tt0 = y_true[base + c0];
        const float tt1 = y_true[base + c1];
        const float tt2 = has2 ? y_true[base + c2] : 0.0f;

        // ---- class log-softmax pieces (c in [5, 85)) ----
        float m = -INFINITY;
        if (c0 >= 5) m = tp0;
        m = fmaxf(m, tp1);
        if (has2) m = fmaxf(m, tp2);
        m = warp_max(m);

        float se = 0.0f;
        if (c0 >= 5) se += expf(tp0 - m);
        se += expf(tp1 - m);
        if (has2) se += expf(tp2 - m);
        se = warp_sum(se);

        // ---- argmax of y_true classes (first-max semantics) ----
        float av = -INFINITY; int ai = 0x7FFFFFFF;
        if (c0 >= 5)            { av = tt0; ai = c0; }
        if (tt1 > av)           { av = tt1; ai = c1; }
        if (has2 && tt2 > av)   { av = tt2; ai = c2; }
        #pragma unroll
        for (int o = 16; o > 0; o >>= 1) {
            float v2 = __shfl_xor_sync(0xFFFFFFFFu, av, o);
            int   i2 = __shfl_xor_sync(0xFFFFFFFFu, ai, o);
            if (v2 > av || (v2 == av && i2 < ai)) { av = v2; ai = i2; }
        }
        // fetch the logit at the true class (ai is warp-uniform now)
        const int slot = ai >> 5;
        float vsel = (slot == 0) ? tp0 : ((slot == 1) ? tp1 : tp2);
        const float logit_true = __shfl_sync(0xFFFFFFFFu, vsel, ai & 31);
        const float ce = logf(se) + m - logit_true;

        // ---- broadcast box raw values (c = 0..4) from lanes 0..4, slot 0 ----
        const float p0 = __shfl_sync(0xFFFFFFFFu, tp0, 0);
        const float p1 = __shfl_sync(0xFFFFFFFFu, tp0, 1);
        const float p2 = __shfl_sync(0xFFFFFFFFu, tp0, 2);
        const float p3 = __shfl_sync(0xFFFFFFFFu, tp0, 3);
        const float p4 = __shfl_sync(0xFFFFFFFFu, tp0, 4);
        const float tx = __shfl_sync(0xFFFFFFFFu, tt0, 0);
        const float ty = __shfl_sync(0xFFFFFFFFu, tt0, 1);
        const float tw = __shfl_sync(0xFFFFFFFFu, tt0, 2);
        const float th = __shfl_sync(0xFFFFFFFFu, tt0, 3);
        const float tconf = __shfl_sync(0xFFFFFFFFu, tt0, 4);

        const float px = sigmoidf(p0) + (float)w;
        const float py = sigmoidf(p1) + (float)h;
        const float pw = expf(p2) * c_anchors[2 * box];
        const float ph = expf(p3) * c_anchors[2 * box + 1];
        const float pc = sigmoidf(p4);

        const float pxmin = px - pw * 0.5f, pxmax = px + pw * 0.5f;
        const float pymin = py - ph * 0.5f, pymax = py + ph * 0.5f;
        const float parea = pw * ph;

        // ---- best IoU over 50 true boxes: lanes split t ----
        float best = 0.0f;
        #pragma unroll
        for (int t = lane; t < NT; t += 32) {
            const float bx = s_tb[t * 4 + 0];
            const float by = s_tb[t * 4 + 1];
            const float bw = s_tb[t * 4 + 2];
            const float bh = s_tb[t * 4 + 3];
            const float iw = fmaxf(fminf(pxmax, bx + bw * 0.5f) - fmaxf(pxmin, bx - bw * 0.5f), 0.0f);
            const float ih = fmaxf(fminf(pymax, by + bh * 0.5f) - fmaxf(pymin, by - bh * 0.5f), 0.0f);
            const float ia = iw * ih;
            const float un = parea + bw * bh - ia;
            best = fmaxf(best, ia / un);
        }
        best = warp_max(best);

        if (lane == 0) {
            // ---- IoU with the ground-truth box at this cell ----
            const float iw = fmaxf(fminf(pxmax, tx + tw * 0.5f) - fmaxf(pxmin, tx - tw * 0.5f), 0.0f);
            const float ih = fmaxf(fminf(pymax, ty + th * 0.5f) - fmaxf(pymin, ty - th * 0.5f), 0.0f);
            const float ia = iw * ih;
            const float un = parea + tw * th - ia;
            const float iou = ia / un;

            const float coord_mask = tconf;           // COORD_FACTOR = 1
            const float true_conf  = iou * tconf;
            const float conf_mask  = ((best < 0.6f) ? 1.0f : 0.0f) * (1.0f - tconf)
                                     + 5.0f * true_conf;      // OBJECT_FACTOR = 5
            const float class_mask = tconf;           // CLASS_FACTOR = 1

            const float s_xy = ((tx - px) * (tx - px) + (ty - py) * (ty - py)) * coord_mask;
            const float s_wh = ((tw - pw) * (tw - pw) + (th - ph) * (th - ph)) * coord_mask;
            const float s_cf = (true_conf - pc) * (true_conf - pc) * conf_mask;
            const float s_cl = ce * class_mask;

            atomicAdd(&s_acc[0], (coord_mask > 0.0f) ? 1.0f : 0.0f);
            atomicAdd(&s_acc[1], (conf_mask  > 0.0f) ? 1.0f : 0.0f);
            atomicAdd(&s_acc[2], (class_mask > 0.0f) ? 1.0f : 0.0f);
            atomicAdd(&s_acc[3], s_xy);
            atomicAdd(&s_acc[4], s_wh);
            atomicAdd(&s_acc[5], s_cf);
            atomicAdd(&s_acc[6], s_cl);
        }
    }
    __syncthreads();
    if (threadIdx.x < 7) atomicAdd(&g_acc[threadIdx.x], s_acc[threadIdx.x]);
}

__global__ void finalize_kernel(float* __restrict__ out) {
    const float nbc = g_acc[0] + 1e-6f;
    const float nbf = g_acc[1] + 1e-6f;
    const float nbl = g_acc[2] + 1e-6f;
    out[0] = g_acc[3] / nbc * 0.5f
           + g_acc[4] / nbc * 0.5f
           + g_acc[5] / nbf * 0.5f
           + g_acc[6] / nbl;
}

extern "C" void kernel_launch(void* const* d_in, const int* in_sizes, int n_in,
                              void* d_out, int out_size) {
    const float* y_true     = (const float*)d_in[0];
    const float* y_pred     = (const float*)d_in[1];
    const float* true_boxes = (const float*)d_in[2];
    float* out = (float*)d_out;

    zero_acc_kernel<<<1, 32>>>();

    // 1024 threads = 32 warps (cells) per block; 27 blocks cover 845 cells/batch
    dim3 grid((CELLS_PER_BATCH + 31) / 32, NBATCH);
    yolo_loss_kernel<<<grid, 1024>>>(y_true, y_pred, true_boxes);

    finalize_kernel<<<1, 1>>>(out);
}

// round 2
// speedup vs baseline: 1.2280x; 1.2280x over previous
#include <cuda_runtime.h>
#include <math.h>

#define GRID_H 13
#define GRID_W 13
#define NBOX   5
#define NCLASS 80
#define NELEM  85
#define NT     50
#define CELLS_PER_BATCH (GRID_H * GRID_W * NBOX)   // 845
#define NBATCH 256

#define NWARPS 16                    // 512-thread blocks
#define CELLS_PER_BLOCK (NWARPS * 2) // 2 cells per warp

__constant__ float c_anchors[10] = {
    0.57273f, 0.677385f, 1.87446f, 2.06253f, 3.33843f,
    5.47434f, 7.88282f, 3.52778f, 9.77052f, 9.16828f
};

// 0 nb_coord, 1 nb_conf, 2 nb_class, 3 s_xy, 4 s_wh, 5 s_conf, 6 s_class
__device__ float g_acc[7];

__global__ void zero_acc_kernel() {
    if (threadIdx.x < 7) g_acc[threadIdx.x] = 0.0f;
}

__device__ __forceinline__ float warp_max(float v) {
    #pragma unroll
    for (int o = 16; o > 0; o >>= 1) v = fmaxf(v, __shfl_xor_sync(0xFFFFFFFFu, v, o));
    return v;
}
__device__ __forceinline__ float warp_sum(float v) {
    #pragma unroll
    for (int o = 16; o > 0; o >>= 1) v += __shfl_xor_sync(0xFFFFFFFFu, v, o);
    return v;
}
__device__ __forceinline__ float fast_sigmoid(float x) {
    return 1.0f / (1.0f + __expf(-x));
}

__global__ __launch_bounds__(32 * NWARPS)
void yolo_loss_kernel(const float* __restrict__ y_true,
                      const float* __restrict__ y_pred,
                      const float* __restrict__ true_boxes) {
    __shared__ float s_tb[NT * 4];
    __shared__ float s_part[NWARPS][8];

    const int b    = blockIdx.y;
    const int warp = threadIdx.x >> 5;
    const int lane = threadIdx.x & 31;

    if (threadIdx.x < NT * 4)
        s_tb[threadIdx.x] = true_boxes[b * (NT * 4) + threadIdx.x];
    __syncthreads();

    const int startCell = blockIdx.x * CELLS_PER_BLOCK;

    // per-cell state, 2 cells per warp for ILP
    int   cellv[2];
    float valid[2];
    float tp0[2], tp1[2], tp2[2], tt0[2], tt1[2], tt2[2];

    const int c0 = lane, c1 = lane + 32, c2 = lane + 64;
    const bool has2 = (c2 < NELEM);        // lane < 21

    // ---------- load phase (12 independent loads in flight) ----------
    #pragma unroll
    for (int k = 0; k < 2; k++) {
        int cell = startCell + warp + k * NWARPS;
        valid[k] = (cell < CELLS_PER_BATCH) ? 1.0f : 0.0f;
        if (cell >= CELLS_PER_BATCH) cell = CELLS_PER_BATCH - 1;  // clamp, mask later
        cellv[k] = cell;
        const unsigned base = (unsigned)(b * CELLS_PER_BATCH + cell) * NELEM;
        tp0[k] = __ldcs(y_pred + base + c0);
        tp1[k] = __ldcs(y_pred + base + c1);
        tp2[k] = has2 ? __ldcs(y_pred + base + c2) : 0.0f;
        tt0[k] = __ldcs(y_true + base + c0);
        tt1[k] = __ldcs(y_true + base + c1);
        tt2[k] = has2 ? __ldcs(y_true + base + c2) : 0.0f;
    }

    float acc0 = 0.f, acc1 = 0.f, acc2 = 0.f, acc3 = 0.f,
          acc4 = 0.f, acc5 = 0.f, acc6 = 0.f;

    // per-cell derived values needed across phases
    float pxmin[2], pxmax[2], pymin[2], pymax[2], parea[2];
    float px[2], py[2], pw[2], ph[2], pc[2];
    float tx[2], ty[2], tw[2], th[2], tconf[2];
    float ce[2];
    float best[2] = {0.f, 0.f};

    // ---------- softmax (no max-pass: logits are small) + argmax + box prep ----------
    #pragma unroll
    for (int k = 0; k < 2; k++) {
        // sum of exps over classes (c >= 5)
        float se = (c0 >= 5) ? __expf(tp0[k]) : 0.0f;
        se += __expf(tp1[k]);
        if (has2) se += __expf(tp2[k]);
        se = warp_sum(se);

        // argmax of y_true classes, first-max semantics
        float av = -INFINITY; int ai = 0x7FFFFFFF;
        if (c0 >= 5)          { av = tt0[k]; ai = c0; }
        if (tt1[k] > av)      { av = tt1[k]; ai = c1; }
        if (has2 && tt2[k] > av) { av = tt2[k]; ai = c2; }
        #pragma unroll
        for (int o = 16; o > 0; o >>= 1) {
            float v2 = __shfl_xor_sync(0xFFFFFFFFu, av, o);
            int   i2 = __shfl_xor_sync(0xFFFFFFFFu, ai, o);
            if (v2 > av || (v2 == av && i2 < ai)) { av = v2; ai = i2; }
        }
        const int slot = ai >> 5;
        float vsel = (slot == 0) ? tp0[k] : ((slot == 1) ? tp1[k] : tp2[k]);
        const float logit_true = __shfl_sync(0xFFFFFFFFu, vsel, ai & 31);
        ce[k] = __logf(se) - logit_true;

        // broadcast raw box scalars
        const float p0 = __shfl_sync(0xFFFFFFFFu, tp0[k], 0);
        const float p1 = __shfl_sync(0xFFFFFFFFu, tp0[k], 1);
        const float p2 = __shfl_sync(0xFFFFFFFFu, tp0[k], 2);
        const float p3 = __shfl_sync(0xFFFFFFFFu, tp0[k], 3);
        const float p4 = __shfl_sync(0xFFFFFFFFu, tp0[k], 4);
        tx[k]    = __shfl_sync(0xFFFFFFFFu, tt0[k], 0);
        ty[k]    = __shfl_sync(0xFFFFFFFFu, tt0[k], 1);
        tw[k]    = __shfl_sync(0xFFFFFFFFu, tt0[k], 2);
        th[k]    = __shfl_sync(0xFFFFFFFFu, tt0[k], 3);
        tconf[k] = __shfl_sync(0xFFFFFFFFu, tt0[k], 4);

        const int box = cellv[k] % NBOX;
        const int w   = (cellv[k] / NBOX) % GRID_W;
        const int h   = cellv[k] / (NBOX * GRID_W);

        px[k] = fast_sigmoid(p0) + (float)w;
        py[k] = fast_sigmoid(p1) + (float)h;
        pw[k] = __expf(p2) * c_anchors[2 * box];
        ph[k] = __expf(p3) * c_anchors[2 * box + 1];
        pc[k] = fast_sigmoid(p4);

        pxmin[k] = px[k] - pw[k] * 0.5f; pxmax[k] = px[k] + pw[k] * 0.5f;
        pymin[k] = py[k] - ph[k] * 0.5f; pymax[k] = py[k] + ph[k] * 0.5f;
        parea[k] = pw[k] * ph[k];
    }

    // ---------- best IoU over 50 true boxes (shared reads amortized over both cells) ----------
    #pragma unroll
    for (int t = lane; t < NT; t += 32) {
        const float bx = s_tb[t * 4 + 0];
        const float by = s_tb[t * 4 + 1];
        const float bw = s_tb[t * 4 + 2];
        const float bh = s_tb[t * 4 + 3];
        const float bxmin = bx - bw * 0.5f, bxmax = bx + bw * 0.5f;
        const float bymin = by - bh * 0.5f, bymax = by + bh * 0.5f;
        const float barea = bw * bh;
        #pragma unroll
        for (int k = 0; k < 2; k++) {
            const float iw = fmaxf(fminf(pxmax[k], bxmax) - fmaxf(pxmin[k], bxmin), 0.0f);
            const float ih = fmaxf(fminf(pymax[k], bymax) - fmaxf(pymin[k], bymin), 0.0f);
            const float ia = iw * ih;
            best[k] = fmaxf(best[k], ia / (parea[k] + barea - ia));
        }
    }
    best[0] = warp_max(best[0]);
    best[1] = warp_max(best[1]);

    // ---------- per-cell scalar losses, accumulated in registers (all lanes compute, lane0 result used) ----------
    #pragma unroll
    for (int k = 0; k < 2; k++) {
        const float iw = fmaxf(fminf(pxmax[k], tx[k] + tw[k] * 0.5f) - fmaxf(pxmin[k], tx[k] - tw[k] * 0.5f), 0.0f);
        const float ih = fmaxf(fminf(pymax[k], ty[k] + th[k] * 0.5f) - fmaxf(pymin[k], ty[k] - th[k] * 0.5f), 0.0f);
        const float ia = iw * ih;
        const float iou = ia / (parea[k] + tw[k] * th[k] - ia);

        const float cm = tconf[k];                  // coord & class mask (factors = 1)
        const float tc = iou * tconf[k];
        const float fm = ((best[k] < 0.6f) ? 1.0f : 0.0f) * (1.0f - tconf[k]) + 5.0f * tc;

        const float v = valid[k];
        acc0 += v * ((cm > 0.0f) ? 1.0f : 0.0f);
        acc1 += v * ((fm > 0.0f) ? 1.0f : 0.0f);
        acc2 += v * ((cm > 0.0f) ? 1.0f : 0.0f);
        acc3 += v * ((tx[k] - px[k]) * (tx[k] - px[k]) + (ty[k] - py[k]) * (ty[k] - py[k])) * cm;
        acc4 += v * ((tw[k] - pw[k]) * (tw[k] - pw[k]) + (th[k] - ph[k]) * (th[k] - ph[k])) * cm;
        acc5 += v * (tc - pc[k]) * (tc - pc[k]) * fm;
        acc6 += v * ce[k] * cm;
    }

    // ---------- block reduction: register -> smem -> warp0 tree -> 7 global atomics ----------
    if (lane == 0) {
        s_part[warp][0] = acc0; s_part[warp][1] = acc1; s_part[warp][2] = acc2;
        s_part[warp][3] = acc3; s_part[warp][4] = acc4; s_part[warp][5] = acc5;
        s_part[warp][6] = acc6;
    }
    __syncthreads();
    if (warp == 0) {
        #pragma unroll
        for (int i = 0; i < 7; i++) {
            float v = (lane < NWARPS) ? s_part[lane][i] : 0.0f;
            v = warp_sum(v);
            if (lane == 0) atomicAdd(&g_acc[i], v);
        }
    }
}

__global__ void finalize_kernel(float* __restrict__ out) {
    const float nbc = g_acc[0] + 1e-6f;
    const float nbf = g_acc[1] + 1e-6f;
    const float nbl = g_acc[2] + 1e-6f;
    out[0] = g_acc[3] / nbc * 0.5f
           + g_acc[4] / nbc * 0.5f
           + g_acc[5] / nbf * 0.5f
           + g_acc[6] / nbl;
}

extern "C" void kernel_launch(void* const* d_in, const int* in_sizes, int n_in,
                              void* d_out, int out_size) {
    const float* y_true     = (const float*)d_in[0];
    const float* y_pred     = (const float*)d_in[1];
    const float* true_boxes = (const float*)d_in[2];
    float* out = (float*)d_out;

    zero_acc_kernel<<<1, 32>>>();

    dim3 grid((CELLS_PER_BATCH + CELLS_PER_BLOCK - 1) / CELLS_PER_BLOCK, NBATCH);
    yolo_loss_kernel<<<grid, 32 * NWARPS>>>(y_true, y_pred, true_boxes);

    finalize_kernel<<<1, 1>>>(out);
}